// round 3
// baseline (speedup 1.0000x reference)
#include <cuda_runtime.h>
#include <math.h>

// ---------------------------------------------------------------------------
// ann2_snn1 — bit-exactness-oriented implementation.
//
// Reference semantics being emulated (JAX/XLA, fp32):
//   h     = relu(inputs @ w1.T + b1)          GEMM: k-sequential FFMA chain
//   drive = sigmoid(h @ w2.T + b2)            sigmoid = 0.5 + 0.5*tanh(0.5x),
//                                             XLA F32 rational tanh
//   scan (T=100):
//     psp = a1*p1 + a2*p2 + drive             separate fp32 roundings
//     cur = psp @ w3.T + b3                   k-sequential FFMA chain
//     v   = sigma*v*(1-s) + cur               separate fp32 roundings
//     s   = (v >= 1)
// ---------------------------------------------------------------------------

#define BM 64
#define BN 64
#define BK 16

#define BATCH 1024
#define H1 500
#define H2 500
#define NIN 784
#define NOUT 10
#define TSTEPS 100

#define HSTR 508            // psp history row stride (mult of 4, conflict-safe)
#define HEAD_THREADS 512

// scratch (no cudaMalloc allowed)
__device__ float g_h[BATCH * H1];
__device__ float g_drive[BATCH * H2];

// XLA F32 tanh: rational approximation (elemental_ir_emitter), Horner w/ fma.
__device__ __forceinline__ float xla_tanh_f32(float x)
{
    const float kMax = 7.90531110763549805f;
    float ax = fabsf(x);
    float xc = fminf(fmaxf(x, -kMax), kMax);
    float x2 = __fmul_rn(xc, xc);

    float np = -2.76076847742355e-16f;
    np = fmaf(np, x2, 2.00018790482477e-13f);
    np = fmaf(np, x2, -8.60467152213735e-11f);
    np = fmaf(np, x2, 5.12229709037114e-08f);
    np = fmaf(np, x2, 1.48572235717979e-05f);
    np = fmaf(np, x2, 6.37261928875436e-04f);
    np = fmaf(np, x2, 4.89352455891786e-03f);
    float num = __fmul_rn(xc, np);

    float dp = 1.19825839466702e-06f;
    dp = fmaf(dp, x2, 1.18534705686654e-04f);
    dp = fmaf(dp, x2, 2.26843463243900e-03f);
    dp = fmaf(dp, x2, 4.89352518554385e-03f);

    float r = __fdiv_rn(num, dp);
    return (ax < 0.0004f) ? x : r;
}

// C[M,N] = act(A[M,K] @ B[N,K]^T + bias[N]);  ACT: 0=relu, 1=xla-sigmoid
// Per-element accumulation is strictly k-ascending, single fp32 acc, FFMA —
// matching Eigen/oneDNN/cublas fp32 GEMM semantics.
template <int ACT>
__global__ __launch_bounds__(256)
void gemm_bias_act(const float* __restrict__ A, const float* __restrict__ B,
                   const float* __restrict__ bias, float* __restrict__ C,
                   int M, int N, int K)
{
    __shared__ float As[BK][BM];
    __shared__ float Bs[BK][BN];

    const int tid = threadIdx.x;
    const int lr  = tid >> 2;
    const int kg  = (tid & 3) << 2;
    const int ty  = tid >> 4;
    const int tx  = tid & 15;
    const int bx  = blockIdx.x, by = blockIdx.y;

    const int gm = by * BM + lr;
    const int gn = bx * BN + lr;

    float acc[4][4] = {};

    for (int k0 = 0; k0 < K; k0 += BK) {
        const int ka = k0 + kg;

        float4 av = make_float4(0.f, 0.f, 0.f, 0.f);
        if (ka + 4 <= K) {
            av = *reinterpret_cast<const float4*>(A + (size_t)gm * K + ka);
        } else {
            float t0 = (ka + 0 < K) ? A[(size_t)gm * K + ka + 0] : 0.f;
            float t1 = (ka + 1 < K) ? A[(size_t)gm * K + ka + 1] : 0.f;
            float t2 = (ka + 2 < K) ? A[(size_t)gm * K + ka + 2] : 0.f;
            float t3 = (ka + 3 < K) ? A[(size_t)gm * K + ka + 3] : 0.f;
            av = make_float4(t0, t1, t2, t3);
        }
        As[kg + 0][lr] = av.x;
        As[kg + 1][lr] = av.y;
        As[kg + 2][lr] = av.z;
        As[kg + 3][lr] = av.w;

        float4 bv = make_float4(0.f, 0.f, 0.f, 0.f);
        if (gn < N) {
            if (ka + 4 <= K) {
                bv = *reinterpret_cast<const float4*>(B + (size_t)gn * K + ka);
            } else {
                float t0 = (ka + 0 < K) ? B[(size_t)gn * K + ka + 0] : 0.f;
                float t1 = (ka + 1 < K) ? B[(size_t)gn * K + ka + 1] : 0.f;
                float t2 = (ka + 2 < K) ? B[(size_t)gn * K + ka + 2] : 0.f;
                float t3 = (ka + 3 < K) ? B[(size_t)gn * K + ka + 3] : 0.f;
                bv = make_float4(t0, t1, t2, t3);
            }
        }
        Bs[kg + 0][lr] = bv.x;
        Bs[kg + 1][lr] = bv.y;
        Bs[kg + 2][lr] = bv.z;
        Bs[kg + 3][lr] = bv.w;

        __syncthreads();

        #pragma unroll
        for (int kk = 0; kk < BK; kk++) {      // k ascending
            float4 a = *reinterpret_cast<const float4*>(&As[kk][ty << 2]);
            float4 b = *reinterpret_cast<const float4*>(&Bs[kk][tx << 2]);
            float ar[4] = {a.x, a.y, a.z, a.w};
            float br[4] = {b.x, b.y, b.z, b.w};
            #pragma unroll
            for (int i = 0; i < 4; i++)
                #pragma unroll
                for (int j = 0; j < 4; j++)
                    acc[i][j] = fmaf(ar[i], br[j], acc[i][j]);  // fused, in order
        }
        __syncthreads();
    }

    const int om = by * BM + (ty << 2);
    const int on = bx * BN + (tx << 2);
    #pragma unroll
    for (int j = 0; j < 4; j++) {
        const int n = on + j;
        if (n >= N) continue;
        const float bb = bias[n];
        #pragma unroll
        for (int i = 0; i < 4; i++) {
            float z = __fadd_rn(acc[i][j], bb);
            float v;
            if (ACT == 0) {
                v = fmaxf(z, 0.f);
            } else {
                float th = xla_tanh_f32(__fmul_rn(0.5f, z));
                v = __fadd_rn(0.5f, __fmul_rn(0.5f, th));
            }
            C[(size_t)(om + i) * N + n] = v;
        }
    }
}

// One block per batch row, 512 threads.
// Phase 1: per-k-lane fp32 psp iteration (separate roundings), history -> smem.
// Phase 2: thread t (<100) runs 10 k-sequential fmaf chains (all outputs o).
// Phase 3: thread o (<10) runs the fp32 membrane scan (separate roundings).
__global__ __launch_bounds__(HEAD_THREADS)
void snn_head(const float* __restrict__ drive, const float* __restrict__ w3,
              const float* __restrict__ b3, float* __restrict__ out,
              float a1, float a2, float sigma)
{
    extern __shared__ float sm[];
    float* hist = sm;                                 // [TSTEPS][HSTR]
    float* w3s  = hist + TSTEPS * HSTR;               // [NOUT][H2]
    float* curs = w3s + NOUT * H2;                    // [TSTEPS][NOUT]

    const int b   = blockIdx.x;
    const int tid = threadIdx.x;

    // stage w3 into smem (row-major [o][k], contiguous — same as input layout)
    for (int i = tid; i < NOUT * H2; i += HEAD_THREADS)
        w3s[i] = w3[i];

    // Phase 1: psp history. Lane owns synapse k; exact reference rounding:
    // psp = ((a1*p1) + (a2*p2)) + drive, each op rounded separately.
    if (tid < H2) {
        const int k = tid;
        float dk = drive[(size_t)b * H2 + k];
        float p1 = 0.f, p2 = 0.f;
        #pragma unroll 4
        for (int t = 0; t < TSTEPS; t++) {
            float m1 = __fmul_rn(a1, p1);
            float m2 = __fmul_rn(a2, p2);
            float ps = __fadd_rn(__fadd_rn(m1, m2), dk);
            hist[t * HSTR + k] = ps;
            p2 = p1;
            p1 = ps;
        }
    }
    __syncthreads();

    // Phase 2: cur[t][o] = sequential-k fmaf chain over psp[t]·w3[o] + b3[o].
    if (tid < TSTEPS) {
        const int t = tid;
        const float4* hrow = reinterpret_cast<const float4*>(hist + t * HSTR);
        float acc[NOUT];
        #pragma unroll
        for (int o = 0; o < NOUT; o++) acc[o] = 0.f;

        #pragma unroll 5
        for (int kq = 0; kq < H2 / 4; kq++) {
            float4 p = hrow[kq];
            #pragma unroll
            for (int o = 0; o < NOUT; o++) {
                float4 w = reinterpret_cast<const float4*>(w3s + o * H2)[kq];
                float a = acc[o];
                a = fmaf(p.x, w.x, a);     // k, k+1, k+2, k+3 in order
                a = fmaf(p.y, w.y, a);
                a = fmaf(p.z, w.z, a);
                a = fmaf(p.w, w.w, a);
                acc[o] = a;
            }
        }
        #pragma unroll
        for (int o = 0; o < NOUT; o++)
            curs[t * NOUT + o] = __fadd_rn(acc[o], b3[o]);
    }
    __syncthreads();

    // Phase 3: membrane scan, v = ((sigma*v)*(1-s)) + cur, separate roundings.
    if (tid < NOUT) {
        const int o = tid;
        float v = 0.f, s = 0.f;
        float* op = out + ((size_t)b * NOUT + o) * TSTEPS;
        #pragma unroll 4
        for (int t = 0; t < TSTEPS; t++) {
            float m = __fmul_rn(__fmul_rn(sigma, v), __fsub_rn(1.0f, s));
            v = __fadd_rn(m, curs[t * NOUT + o]);
            s = (v >= 1.0f) ? 1.0f : 0.0f;
            op[t] = s;
        }
    }
}

extern "C" void kernel_launch(void* const* d_in, const int* in_sizes, int n_in,
                              void* d_out, int out_size)
{
    const float* inputs = (const float*)d_in[0];  // [1024, 784]
    const float* w1     = (const float*)d_in[1];  // [500, 784]
    const float* b1     = (const float*)d_in[2];  // [500]
    const float* w2     = (const float*)d_in[3];  // [500, 500]
    const float* b2     = (const float*)d_in[4];  // [500]
    const float* w3     = (const float*)d_in[5];  // [10, 500]
    const float* b3     = (const float*)d_in[6];  // [10]
    float* out          = (float*)d_out;          // [1024, 10, 100]

    float *h = nullptr, *drive = nullptr;
    cudaGetSymbolAddress((void**)&h, g_h);
    cudaGetSymbolAddress((void**)&drive, g_drive);

    // constants: python doubles rounded once to fp32 (as in the jitted graph)
    const double em = exp(-1.0 / 4.0);   // tau_m = 4
    const double es = exp(-1.0 / 1.0);   // tau_s = 1
    const float a1f = (float)(em + es);
    const float a2f = (float)(-em * es);
    const float sgf = (float)em;

    dim3 blk(256);
    dim3 g1((H1 + BN - 1) / BN, (BATCH + BM - 1) / BM);   // (8, 16)
    gemm_bias_act<0><<<g1, blk>>>(inputs, w1, b1, h, BATCH, H1, NIN);
    gemm_bias_act<1><<<g1, blk>>>(h, w2, b2, drive, BATCH, H2, H1);

    const int head_smem = (TSTEPS * HSTR + NOUT * H2 + TSTEPS * NOUT) * sizeof(float);
    cudaFuncSetAttribute(snn_head, cudaFuncAttributeMaxDynamicSharedMemorySize,
                         head_smem);
    snn_head<<<BATCH, HEAD_THREADS, head_smem>>>(drive, w3, b3, out,
                                                 a1f, a2f, sgf);
}

// round 8
// speedup vs baseline: 1.2185x; 1.2185x over previous
#include <cuda_runtime.h>
#include <math.h>

// ---------------------------------------------------------------------------
// ann2_snn1 — bit-exact emulation of the JAX/XLA fp32 reference, optimized.
//   h     = relu(inputs @ w1.T + b1)        k-sequential FFMA chains
//   drive = sigmoid(h @ w2.T + b2)          sigmoid = 0.5+0.5*tanh(0.5x), XLA tanh
//   scan: psp = a1*p1 + a2*p2 + drive       separate fp32 roundings
//         cur = psp @ w3.T + b3             k-sequential FFMA chains
//         v   = sigma*v*(1-s) + cur ; s = (v>=1)
// Perf: double-buffered GEMMs (1 sync/iter, gmem prefetch); head k-chunked so
// smem fits 2 blocks/SM; phase-2 uses 500 threads with hist reuse.
// ---------------------------------------------------------------------------

#define BM 64
#define BN 64
#define BK 16

#define BATCH 1024
#define H1 500
#define H2 500
#define NIN 784
#define NOUT 10
#define TSTEPS 100

#define HT 512              // head threads
#define HROW 132            // hist row stride in floats (33 float4, odd)

// scratch (no cudaMalloc allowed)
__device__ float g_h[BATCH * H1];
__device__ float g_drive[BATCH * H2];

// XLA F32 tanh rational approximation (matches reference bit-for-bit).
__device__ __forceinline__ float xla_tanh_f32(float x)
{
    const float kMax = 7.90531110763549805f;
    float ax = fabsf(x);
    float xc = fminf(fmaxf(x, -kMax), kMax);
    float x2 = __fmul_rn(xc, xc);

    float np = -2.76076847742355e-16f;
    np = fmaf(np, x2, 2.00018790482477e-13f);
    np = fmaf(np, x2, -8.60467152213735e-11f);
    np = fmaf(np, x2, 5.12229709037114e-08f);
    np = fmaf(np, x2, 1.48572235717979e-05f);
    np = fmaf(np, x2, 6.37261928875436e-04f);
    np = fmaf(np, x2, 4.89352455891786e-03f);
    float num = __fmul_rn(xc, np);

    float dp = 1.19825839466702e-06f;
    dp = fmaf(dp, x2, 1.18534705686654e-04f);
    dp = fmaf(dp, x2, 2.26843463243900e-03f);
    dp = fmaf(dp, x2, 4.89352518554385e-03f);

    float r = __fdiv_rn(num, dp);
    return (ax < 0.0004f) ? x : r;
}

__device__ __forceinline__ float4 ld4_guard(const float* row, int k, int K)
{
    if (k + 4 <= K)
        return *reinterpret_cast<const float4*>(row + k);
    float4 v;
    v.x = (k + 0 < K) ? row[k + 0] : 0.f;
    v.y = (k + 1 < K) ? row[k + 1] : 0.f;
    v.z = (k + 2 < K) ? row[k + 2] : 0.f;
    v.w = (k + 3 < K) ? row[k + 3] : 0.f;
    return v;
}

// C[M,N] = act(A[M,K] @ B[N,K]^T + bias[N]); ACT 0=relu, 1=xla-sigmoid.
// Double-buffered smem pipeline, ONE __syncthreads per K-tile. Per-element
// accumulation strictly k-ascending single-acc fmaf (bit-exact contract).
template <int ACT>
__global__ __launch_bounds__(256)
void gemm_bias_act(const float* __restrict__ A, const float* __restrict__ B,
                   const float* __restrict__ bias, float* __restrict__ C,
                   int M, int N, int K)
{
    __shared__ float As[2][BK][BM];
    __shared__ float Bs[2][BK][BN];

    const int tid = threadIdx.x;
    const int lr  = tid >> 2;         // 0..63 row within tile (loading)
    const int kg  = (tid & 3) << 2;   // 0,4,8,12 k-subgroup (loading)
    const int ty  = tid >> 4;         // 0..15
    const int tx  = tid & 15;         // 0..15

    const int gm = blockIdx.y * BM + lr;   // M=1024, always valid
    const int gn = blockIdx.x * BN + lr;   // may exceed N

    const float* Arow = A + (size_t)gm * K;
    const float* Brow = B + (size_t)gn * K;
    const bool bn_ok  = (gn < N);

    const int nIter = (K + BK - 1) / BK;

    // prologue: tile 0 -> buf 0
    {
        float4 av = ld4_guard(Arow, kg, K);
        float4 bv = bn_ok ? ld4_guard(Brow, kg, K)
                          : make_float4(0.f, 0.f, 0.f, 0.f);
        As[0][kg + 0][lr] = av.x; As[0][kg + 1][lr] = av.y;
        As[0][kg + 2][lr] = av.z; As[0][kg + 3][lr] = av.w;
        Bs[0][kg + 0][lr] = bv.x; Bs[0][kg + 1][lr] = bv.y;
        Bs[0][kg + 2][lr] = bv.z; Bs[0][kg + 3][lr] = bv.w;
    }
    __syncthreads();

    float acc[4][4] = {};
    int buf = 0;

    for (int it = 0; it < nIter; ++it) {
        float4 av2, bv2;
        const bool more = (it + 1 < nIter);
        if (more) {
            const int ka = (it + 1) * BK + kg;
            av2 = ld4_guard(Arow, ka, K);
            bv2 = bn_ok ? ld4_guard(Brow, ka, K)
                        : make_float4(0.f, 0.f, 0.f, 0.f);
        }

        #pragma unroll
        for (int kk = 0; kk < BK; kk++) {             // k ascending
            float4 a = *reinterpret_cast<const float4*>(&As[buf][kk][ty << 2]);
            float4 b = *reinterpret_cast<const float4*>(&Bs[buf][kk][tx << 2]);
            float ar[4] = {a.x, a.y, a.z, a.w};
            float br[4] = {b.x, b.y, b.z, b.w};
            #pragma unroll
            for (int i = 0; i < 4; i++)
                #pragma unroll
                for (int j = 0; j < 4; j++)
                    acc[i][j] = fmaf(ar[i], br[j], acc[i][j]);
        }

        if (more) {
            const int nb = buf ^ 1;  // safe: consumed tile's last read was before prior sync
            As[nb][kg + 0][lr] = av2.x; As[nb][kg + 1][lr] = av2.y;
            As[nb][kg + 2][lr] = av2.z; As[nb][kg + 3][lr] = av2.w;
            Bs[nb][kg + 0][lr] = bv2.x; Bs[nb][kg + 1][lr] = bv2.y;
            Bs[nb][kg + 2][lr] = bv2.z; Bs[nb][kg + 3][lr] = bv2.w;
        }
        __syncthreads();
        buf ^= 1;
    }

    const int om = blockIdx.y * BM + (ty << 2);
    const int on = blockIdx.x * BN + (tx << 2);
    #pragma unroll
    for (int j = 0; j < 4; j++) {
        const int n = on + j;
        if (n >= N) continue;
        const float bb = bias[n];
        #pragma unroll
        for (int i = 0; i < 4; i++) {
            float z = __fadd_rn(acc[i][j], bb);
            float v;
            if (ACT == 0) {
                v = fmaxf(z, 0.f);
            } else {
                float th = xla_tanh_f32(__fmul_rn(0.5f, z));
                v = __fadd_rn(0.5f, __fmul_rn(0.5f, th));
            }
            C[(size_t)(om + i) * N + n] = v;
        }
    }
}

// Head: one block per batch row, 512 threads, K chunked {128,128,128,116} so
// dynamic smem (~81KB) fits 2 blocks/SM. Phase-2 accumulators live in
// registers across chunks -> each (t,o) chain is one k-ascending fmaf chain.
__global__ __launch_bounds__(HT, 2)
void snn_head(const float* __restrict__ drive, const float* __restrict__ w3,
              const float* __restrict__ b3, float* __restrict__ out,
              float a1, float a2, float sigma)
{
    extern __shared__ float sm[];
    float* hist = sm;                       // [TSTEPS][HROW]
    float* w3s  = sm + TSTEPS * HROW;       // [NOUT][H2] = 5000
    float* curs = w3s + NOUT * H2;          // [TSTEPS][NOUT] = 1000
    float* spk  = curs + TSTEPS * NOUT;     // [NOUT][TSTEPS] = 1000

    const int b   = blockIdx.x;
    const int tid = threadIdx.x;

    for (int i = tid; i < NOUT * H2; i += HT)
        w3s[i] = w3[i];

    const int t  = tid % TSTEPS;   // phase-2 time index (tid < 500)
    const int og = tid / TSTEPS;   // phase-2 output pair 0..4
    float acc0 = 0.f, acc1 = 0.f;

    #pragma unroll
    for (int c = 0; c < 4; ++c) {
        const int k0   = c * 128;
        const int klen = (c < 3) ? 128 : 116;

        // Phase 1: per-k psp recurrence for this k-chunk (exact roundings)
        if (tid < klen) {
            const float d = drive[(size_t)b * H2 + k0 + tid];
            float p1 = 0.f, p2 = 0.f;
            #pragma unroll 4
            for (int tt = 0; tt < TSTEPS; ++tt) {
                float ps = __fadd_rn(
                    __fadd_rn(__fmul_rn(a1, p1), __fmul_rn(a2, p2)), d);
                hist[tt * HROW + tid] = ps;
                p2 = p1;
                p1 = ps;
            }
        }
        __syncthreads();

        // Phase 2: continue k-ascending fmaf chains for (t, 2og) and (t, 2og+1)
        if (tid < 500) {
            const float4* h4 = reinterpret_cast<const float4*>(hist) + t * (HROW / 4);
            const float4* wA = reinterpret_cast<const float4*>(w3s + (og * 2 + 0) * H2 + k0);
            const float4* wB = reinterpret_cast<const float4*>(w3s + (og * 2 + 1) * H2 + k0);
            const int nq = klen >> 2;
            #pragma unroll 8
            for (int j = 0; j < nq; ++j) {
                float4 h = h4[j];
                float4 a = wA[j];
                float4 w = wB[j];
                acc0 = fmaf(h.x, a.x, acc0);
                acc0 = fmaf(h.y, a.y, acc0);
                acc0 = fmaf(h.z, a.z, acc0);
                acc0 = fmaf(h.w, a.w, acc0);
                acc1 = fmaf(h.x, w.x, acc1);
                acc1 = fmaf(h.y, w.y, acc1);
                acc1 = fmaf(h.z, w.z, acc1);
                acc1 = fmaf(h.w, w.w, acc1);
            }
        }
        __syncthreads();   // hist reused next chunk
    }

    if (tid < 500) {
        curs[t * NOUT + og * 2 + 0] = __fadd_rn(acc0, b3[og * 2 + 0]);
        curs[t * NOUT + og * 2 + 1] = __fadd_rn(acc1, b3[og * 2 + 1]);
    }
    __syncthreads();

    // Phase 3: membrane scan, separate roundings, spikes to smem
    if (tid < NOUT) {
        float v = 0.f, s = 0.f;
        #pragma unroll 4
        for (int tt = 0; tt < TSTEPS; ++tt) {
            float m = __fmul_rn(__fmul_rn(sigma, v), __fsub_rn(1.0f, s));
            v = __fadd_rn(m, curs[tt * NOUT + tid]);
            s = (v >= 1.0f) ? 1.0f : 0.0f;
            spk[tid * TSTEPS + tt] = s;    // [o][t] matches out layout
        }
    }
    __syncthreads();

    // coalesced writeback: 1000 contiguous floats per block
    float4* o4 = reinterpret_cast<float4*>(out + (size_t)b * NOUT * TSTEPS);
    const float4* s4 = reinterpret_cast<const float4*>(spk);
    if (tid < NOUT * TSTEPS / 4)
        o4[tid] = s4[tid];
}

extern "C" void kernel_launch(void* const* d_in, const int* in_sizes, int n_in,
                              void* d_out, int out_size)
{
    const float* inputs = (const float*)d_in[0];  // [1024, 784]
    const float* w1     = (const float*)d_in[1];  // [500, 784]
    const float* b1     = (const float*)d_in[2];  // [500]
    const float* w2     = (const float*)d_in[3];  // [500, 500]
    const float* b2     = (const float*)d_in[4];  // [500]
    const float* w3     = (const float*)d_in[5];  // [10, 500]
    const float* b3     = (const float*)d_in[6];  // [10]
    float* out          = (float*)d_out;          // [1024, 10, 100]

    float *h = nullptr, *drive = nullptr;
    cudaGetSymbolAddress((void**)&h, g_h);
    cudaGetSymbolAddress((void**)&drive, g_drive);

    const double em = exp(-1.0 / 4.0);
    const double es = exp(-1.0 / 1.0);
    const float a1f = (float)(em + es);
    const float a2f = (float)(-em * es);
    const float sgf = (float)em;

    dim3 blk(256);
    dim3 g1((H1 + BN - 1) / BN, (BATCH + BM - 1) / BM);   // (8, 16)
    gemm_bias_act<0><<<g1, blk>>>(inputs, w1, b1, h, BATCH, H1, NIN);
    gemm_bias_act<1><<<g1, blk>>>(h, w2, b2, drive, BATCH, H2, H1);

    const int head_smem =
        (TSTEPS * HROW + NOUT * H2 + 2 * TSTEPS * NOUT) * sizeof(float);
    cudaFuncSetAttribute(snn_head, cudaFuncAttributeMaxDynamicSharedMemorySize,
                         head_smem);
    snn_head<<<BATCH, HT, head_smem>>>(drive, w3, b3, out, a1f, a2f, sgf);
}